// round 3
// baseline (speedup 1.0000x reference)
#include <cuda_runtime.h>

#define BB 4
#define NN 512
#define MM 512
#define LD 512
#define AG 256
#define ROWS (BB * NN)   // 2048

__device__ float g_dl[ROWS * AG];   // [row][a]
__device__ float g_cl[ROWS * AG];   // [row][a]

__device__ __forceinline__ float fast_tanh(float x) {
    float y;
    asm("tanh.approx.f32 %0, %1;" : "=f"(y) : "f"(x));
    return y;
}

// ---------------------------------------------------------------------------
// Projection GEMM: out[row][a] = sum_k in[row][k] * W[k][a] + bias[a]
// BM=64, BN=64, BK=16, 256 threads, 4x4/thread, double-buffered smem.
// grid (32 row-tiles, 4 col-tiles, 2 gemms) = 256 blocks.
// ---------------------------------------------------------------------------
__global__ __launch_bounds__(256) void proj_kernel(
    const float* __restrict__ data, const float* __restrict__ crit,
    const float* __restrict__ Wl, const float* __restrict__ bl,
    const float* __restrict__ Wr, const float* __restrict__ br)
{
    __shared__ float As[2][16][68];   // [buf][k][m], pad 68 (16B-aligned rows)
    __shared__ float Bs[2][16][68];   // [buf][k][n]

    const float* A; const float* W; const float* bias; float* out;
    if (blockIdx.z == 0) { A = data; W = Wl; bias = bl; out = g_dl; }
    else                 { A = crit; W = Wr; bias = br; out = g_cl; }
    const int row0 = blockIdx.x * 64;
    const int col0 = blockIdx.y * 64;

    const int tid = threadIdx.x;
    const int ar  = tid >> 2;            // 0..63
    const int ac  = (tid & 3) << 2;      // 0,4,8,12
    const int bro = tid >> 4;            // 0..15
    const int bco = (tid & 15) << 2;     // 0..60
    const int ty  = tid >> 4;            // 0..15 -> rows 4ty
    const int tx  = tid & 15;            // 0..15 -> cols 4tx

    const float* Aptr = A + (row0 + ar) * LD + ac;
    const float* Wptr = W + bro * AG + col0 + bco;

    float acc[4][4];
#pragma unroll
    for (int i = 0; i < 4; i++)
#pragma unroll
        for (int j = 0; j < 4; j++) acc[i][j] = 0.f;

    // prologue: chunk 0 -> buf 0
    {
        float4 av = *(const float4*)(Aptr);
        float4 bv = *(const float4*)(Wptr);
        As[0][ac + 0][ar] = av.x;
        As[0][ac + 1][ar] = av.y;
        As[0][ac + 2][ar] = av.z;
        As[0][ac + 3][ar] = av.w;
        *(float4*)&Bs[0][bro][bco] = bv;
    }
    __syncthreads();

    int cur = 0;
    for (int k0 = 0; k0 < LD; k0 += 16) {
        float4 an, bn;
        const bool more = (k0 + 16) < LD;
        if (more) {
            an = *(const float4*)(Aptr + k0 + 16);
            bn = *(const float4*)(Wptr + (size_t)(k0 + 16) * AG);
        }
#pragma unroll
        for (int k = 0; k < 16; k++) {
            float a[4], b[4];
            *(float4*)a = *(const float4*)&As[cur][k][ty << 2];
            *(float4*)b = *(const float4*)&Bs[cur][k][tx << 2];
#pragma unroll
            for (int i = 0; i < 4; i++)
#pragma unroll
                for (int j = 0; j < 4; j++)
                    acc[i][j] = fmaf(a[i], b[j], acc[i][j]);
        }
        if (more) {
            int nxt = cur ^ 1;
            As[nxt][ac + 0][ar] = an.x;
            As[nxt][ac + 1][ar] = an.y;
            As[nxt][ac + 2][ar] = an.z;
            As[nxt][ac + 3][ar] = an.w;
            *(float4*)&Bs[nxt][bro][bco] = bn;
            __syncthreads();
            cur = nxt;
        }
    }

#pragma unroll
    for (int i = 0; i < 4; i++) {
        int row = row0 + (ty << 2) + i;
        int c   = col0 + (tx << 2);
        float4 v;
        v.x = acc[i][0] + bias[c + 0];
        v.y = acc[i][1] + bias[c + 1];
        v.z = acc[i][2] + bias[c + 2];
        v.w = acc[i][3] + bias[c + 3];
        *(float4*)(out + row * AG + c) = v;
    }
}

// ---------------------------------------------------------------------------
// Distance kernel: dists[b,n,m] = sum_a tanh(dl[b,n,a] + cl[b,m,a]) * agg[a]
// 32x32 tile / block (grid 1024 -> 98.8% wave balance), 256 threads, 2x2/thread.
// a staged in chunks of 64, a-major smem, stride 34 (even -> float2 reads).
// ---------------------------------------------------------------------------
__global__ __launch_bounds__(256) void dist_kernel(
    const float* __restrict__ agg, float* __restrict__ out)
{
    __shared__ float dls[64][34];
    __shared__ float cls[64][34];
    __shared__ float aggs[AG];

    const int b  = blockIdx.z;
    const int n0 = blockIdx.x << 5;
    const int m0 = blockIdx.y << 5;
    const int tid = threadIdx.x;
    const int ty2 = (tid >> 4) << 1;   // n rows ty2, ty2+1
    const int tx2 = (tid & 15) << 1;   // m cols tx2, tx2+1

    aggs[tid] = agg[tid];

    const float* dlb = g_dl + (size_t)(b * NN + n0) * AG;
    const float* clb = g_cl + (size_t)(b * MM + m0) * AG;

    float a00 = 0.f, a01 = 0.f, a10 = 0.f, a11 = 0.f;

    for (int a0 = 0; a0 < AG; a0 += 64) {
        __syncthreads();   // protect previous chunk reads (covers aggs on iter 0)
#pragma unroll
        for (int h = 0; h < 2; h++) {
            int idx = tid + (h << 8);       // 0..511
            int r   = idx >> 4;             // 0..31
            int a4  = (idx & 15) << 2;      // 0..60
            float4 v = *(const float4*)(dlb + r * AG + a0 + a4);
            dls[a4 + 0][r] = v.x;
            dls[a4 + 1][r] = v.y;
            dls[a4 + 2][r] = v.z;
            dls[a4 + 3][r] = v.w;
            float4 w = *(const float4*)(clb + r * AG + a0 + a4);
            cls[a4 + 0][r] = w.x;
            cls[a4 + 1][r] = w.y;
            cls[a4 + 2][r] = w.z;
            cls[a4 + 3][r] = w.w;
        }
        __syncthreads();

#pragma unroll 4
        for (int a = 0; a < 64; a++) {
            float2 d = *(const float2*)&dls[a][ty2];
            float2 c = *(const float2*)&cls[a][tx2];
            float g = aggs[a0 + a];
            a00 = fmaf(fast_tanh(d.x + c.x), g, a00);
            a01 = fmaf(fast_tanh(d.x + c.y), g, a01);
            a10 = fmaf(fast_tanh(d.y + c.x), g, a10);
            a11 = fmaf(fast_tanh(d.y + c.y), g, a11);
        }
    }

    float* o0 = out + ((size_t)(b * NN + n0 + ty2) << 9) + m0 + tx2;
    float* o1 = o0 + MM;
    *(float2*)o0 = make_float2(a00, a01);
    *(float2*)o1 = make_float2(a10, a11);
}

extern "C" void kernel_launch(void* const* d_in, const int* in_sizes, int n_in,
                              void* d_out, int out_size) {
    const float* data = (const float*)d_in[0];
    const float* crit = (const float*)d_in[1];
    const float* Wl   = (const float*)d_in[2];
    const float* bl   = (const float*)d_in[3];
    const float* Wr   = (const float*)d_in[4];
    const float* br   = (const float*)d_in[5];
    const float* agg  = (const float*)d_in[6];
    float* out = (float*)d_out;

    proj_kernel<<<dim3(32, 4, 2), 256>>>(data, crit, Wl, bl, Wr, br);
    dist_kernel<<<dim3(16, 16, 4), 256>>>(agg, out);
}

// round 5
// speedup vs baseline: 1.0003x; 1.0003x over previous
#include <cuda_runtime.h>
#include <cuda_fp16.h>

#define BB 4
#define NN 512
#define MM 512
#define LD 512
#define AG 256
#define ROWS (BB * NN)   // 2048

__device__ float g_dl[ROWS * AG];   // [row][a]
__device__ float g_cl[ROWS * AG];   // [row][a]

__device__ __forceinline__ unsigned tanh_h2(unsigned x) {
    unsigned y;
    asm("tanh.approx.f16x2 %0, %1;" : "=r"(y) : "r"(x));
    return y;
}
__device__ __forceinline__ unsigned hadd2_raw(unsigned a, unsigned b) {
    unsigned r;
    asm("add.f16x2 %0, %1, %2;" : "=r"(r) : "r"(a), "r"(b));
    return r;
}
__device__ __forceinline__ __half2 u2h2(unsigned v) {
    __half2 h;
    *(unsigned*)&h = v;
    return h;
}

// ---------------------------------------------------------------------------
// Projection GEMM: out[row][a] = in[row][:] @ W + bias
// BM=64, BN=64, BK=16, 256 threads, 4x4/thread, double-buffered smem.
// ---------------------------------------------------------------------------
__global__ __launch_bounds__(256) void proj_kernel(
    const float* __restrict__ data, const float* __restrict__ crit,
    const float* __restrict__ Wl, const float* __restrict__ bl,
    const float* __restrict__ Wr, const float* __restrict__ br)
{
    __shared__ float As[2][16][68];
    __shared__ float Bs[2][16][68];

    const float* A; const float* W; const float* bias; float* out;
    if (blockIdx.z == 0) { A = data; W = Wl; bias = bl; out = g_dl; }
    else                 { A = crit; W = Wr; bias = br; out = g_cl; }
    const int row0 = blockIdx.x * 64;
    const int col0 = blockIdx.y * 64;

    const int tid = threadIdx.x;
    const int ar  = tid >> 2;
    const int ac  = (tid & 3) << 2;
    const int bro = tid >> 4;
    const int bco = (tid & 15) << 2;
    const int ty  = tid >> 4;
    const int tx  = tid & 15;

    const float* Aptr = A + (row0 + ar) * LD + ac;
    const float* Wptr = W + bro * AG + col0 + bco;

    float acc[4][4];
#pragma unroll
    for (int i = 0; i < 4; i++)
#pragma unroll
        for (int j = 0; j < 4; j++) acc[i][j] = 0.f;

    {
        float4 av = *(const float4*)(Aptr);
        float4 bv = *(const float4*)(Wptr);
        As[0][ac + 0][ar] = av.x;
        As[0][ac + 1][ar] = av.y;
        As[0][ac + 2][ar] = av.z;
        As[0][ac + 3][ar] = av.w;
        *(float4*)&Bs[0][bro][bco] = bv;
    }
    __syncthreads();

    int cur = 0;
    for (int k0 = 0; k0 < LD; k0 += 16) {
        float4 an, bn;
        const bool more = (k0 + 16) < LD;
        if (more) {
            an = *(const float4*)(Aptr + k0 + 16);
            bn = *(const float4*)(Wptr + (size_t)(k0 + 16) * AG);
        }
#pragma unroll
        for (int k = 0; k < 16; k++) {
            float a[4], b[4];
            *(float4*)a = *(const float4*)&As[cur][k][ty << 2];
            *(float4*)b = *(const float4*)&Bs[cur][k][tx << 2];
#pragma unroll
            for (int i = 0; i < 4; i++)
#pragma unroll
                for (int j = 0; j < 4; j++)
                    acc[i][j] = fmaf(a[i], b[j], acc[i][j]);
        }
        if (more) {
            int nxt = cur ^ 1;
            As[nxt][ac + 0][ar] = an.x;
            As[nxt][ac + 1][ar] = an.y;
            As[nxt][ac + 2][ar] = an.z;
            As[nxt][ac + 3][ar] = an.w;
            *(float4*)&Bs[nxt][bro][bco] = bn;
            __syncthreads();
            cur = nxt;
        }
    }

#pragma unroll
    for (int i = 0; i < 4; i++) {
        int row = row0 + (ty << 2) + i;
        int c   = col0 + (tx << 2);
        float4 v;
        v.x = acc[i][0] + bias[c + 0];
        v.y = acc[i][1] + bias[c + 1];
        v.z = acc[i][2] + bias[c + 2];
        v.w = acc[i][3] + bias[c + 3];
        *(float4*)(out + row * AG + c) = v;
    }
}

// ---------------------------------------------------------------------------
// Distance kernel (fp16x2 tanh): dists[b,n,m] = sum_a tanh(dl+cl)*agg
// 32x32 tile / block (grid 1024), 128 threads, per-thread 2(n) x 4(m).
// dl/cl staged a-major in smem as fp16, row stride 36 halves (72B-aligned).
// MUFU.TANH.H2: 2 tanh per MUFU op -> half the fp32 MUFU floor.
// fp32 accumulation preserves output precision.
// ---------------------------------------------------------------------------
__global__ __launch_bounds__(128) void dist_kernel(
    const float* __restrict__ agg, float* __restrict__ out)
{
    __shared__ __half dls[64][36];
    __shared__ __half cls[64][36];
    __shared__ float  aggs[AG];

    const int b  = blockIdx.z;
    const int n0 = blockIdx.x << 5;
    const int m0 = blockIdx.y << 5;
    const int tid = threadIdx.x;
    const int ty  = tid >> 3;          // 0..15 -> n rows 2ty, 2ty+1
    const int tx  = tid & 7;           // 0..7  -> m cols 4tx .. 4tx+3

    aggs[tid]       = agg[tid];
    aggs[tid + 128] = agg[tid + 128];

    const float* dlb = g_dl + (size_t)(b * NN + n0) * AG;
    const float* clb = g_cl + (size_t)(b * MM + m0) * AG;

    float a00 = 0.f, a01 = 0.f, a02 = 0.f, a03 = 0.f;
    float a10 = 0.f, a11 = 0.f, a12 = 0.f, a13 = 0.f;

    for (int a0 = 0; a0 < AG; a0 += 64) {
        __syncthreads();   // protect previous chunk reads (covers aggs on iter 0)
#pragma unroll
        for (int h = 0; h < 4; h++) {
            int idx = tid + (h << 7);        // 0..511
            int r   = idx >> 4;              // 0..31
            int a4  = (idx & 15) << 2;       // 0..60
            float4 v = *(const float4*)(dlb + r * AG + a0 + a4);
            dls[a4 + 0][r] = __float2half_rn(v.x);
            dls[a4 + 1][r] = __float2half_rn(v.y);
            dls[a4 + 2][r] = __float2half_rn(v.z);
            dls[a4 + 3][r] = __float2half_rn(v.w);
            float4 w = *(const float4*)(clb + r * AG + a0 + a4);
            cls[a4 + 0][r] = __float2half_rn(w.x);
            cls[a4 + 1][r] = __float2half_rn(w.y);
            cls[a4 + 2][r] = __float2half_rn(w.z);
            cls[a4 + 3][r] = __float2half_rn(w.w);
        }
        __syncthreads();

#pragma unroll 8
        for (int a = 0; a < 64; a++) {
            unsigned dpair = *(const unsigned*)&dls[a][ty << 1];   // (d0,d1)
            uint2    cq    = *(const uint2*)&cls[a][tx << 2];      // (c0..c3)
            unsigned d00 = __byte_perm(dpair, 0, 0x1010);          // (d0,d0)
            unsigned d11 = __byte_perm(dpair, 0, 0x3232);          // (d1,d1)

            __half2 t00 = u2h2(tanh_h2(hadd2_raw(d00, cq.x)));
            __half2 t01 = u2h2(tanh_h2(hadd2_raw(d00, cq.y)));
            __half2 t10 = u2h2(tanh_h2(hadd2_raw(d11, cq.x)));
            __half2 t11 = u2h2(tanh_h2(hadd2_raw(d11, cq.y)));

            float g = aggs[a0 + a];
            a00 = fmaf(__low2float(t00),  g, a00);
            a01 = fmaf(__high2float(t00), g, a01);
            a02 = fmaf(__low2float(t01),  g, a02);
            a03 = fmaf(__high2float(t01), g, a03);
            a10 = fmaf(__low2float(t10),  g, a10);
            a11 = fmaf(__high2float(t10), g, a11);
            a12 = fmaf(__low2float(t11),  g, a12);
            a13 = fmaf(__high2float(t11), g, a13);
        }
    }

    float* o0 = out + ((size_t)(b * NN + n0 + (ty << 1)) << 9) + m0 + (tx << 2);
    float* o1 = o0 + MM;
    *(float4*)o0 = make_float4(a00, a01, a02, a03);
    *(float4*)o1 = make_float4(a10, a11, a12, a13);
}

extern "C" void kernel_launch(void* const* d_in, const int* in_sizes, int n_in,
                              void* d_out, int out_size) {
    const float* data = (const float*)d_in[0];
    const float* crit = (const float*)d_in[1];
    const float* Wl   = (const float*)d_in[2];
    const float* bl   = (const float*)d_in[3];
    const float* Wr   = (const float*)d_in[4];
    const float* br   = (const float*)d_in[5];
    const float* agg  = (const float*)d_in[6];
    float* out = (float*)d_out;

    proj_kernel<<<dim3(32, 4, 2), 256>>>(data, crit, Wl, bl, Wr, br);
    dist_kernel<<<dim3(16, 16, 4), 128>>>(agg, out);
}